// round 3
// baseline (speedup 1.0000x reference)
#include <cuda_runtime.h>

#define BB 2
#define NN 512
#define DD 512
#define HH 8
#define EE 128

// Scratch (no cudaMalloc allowed): o2 activations + factored tensor A
__device__ float g_o2[BB * NN * HH];              // 8K floats
__device__ float g_A [(size_t)BB * NN * EE * HH]; // 1M floats = 4 MB

// ---------------------------------------------------------------------------
// Kernel 1: per (b,n) row — compute o12 = x@W12^T + b12, store o2 half to
// global scratch, and compute A[e][j] = sum_i o1[i] * W3[e, i*8+j].
// ---------------------------------------------------------------------------
__global__ void __launch_bounds__(512) prep_kernel(
    const float* __restrict__ x,    // (B,N,D)
    const float* __restrict__ W12,  // (16,D)
    const float* __restrict__ b12,  // (16,)
    const float* __restrict__ W3)   // (E,64)
{
    const int bn   = blockIdx.x;        // 0..B*N-1
    const int tid  = threadIdx.x;       // 512 threads = 16 warps
    const int warp = tid >> 5;
    const int lane = tid & 31;

    __shared__ float xs[DD];
    __shared__ float o1s[HH];

    const float* xrow = x + (size_t)bn * DD;
    // vectorized row load into smem
    for (int i = tid; i < DD / 4; i += 512)
        reinterpret_cast<float4*>(xs)[i] = reinterpret_cast<const float4*>(xrow)[i];
    __syncthreads();

    // warp w computes o12[bn, w]  (w in 0..15)
    float sum = 0.f;
    const float* w = W12 + warp * DD;
    #pragma unroll 4
    for (int i = lane; i < DD; i += 32)
        sum += xs[i] * w[i];
    #pragma unroll
    for (int o = 16; o; o >>= 1)
        sum += __shfl_xor_sync(0xffffffffu, sum, o);

    if (lane == 0) {
        sum += b12[warp];
        if (warp < HH) o1s[warp] = sum;
        else           g_o2[bn * HH + (warp - HH)] = sum;
    }
    __syncthreads();

    // threads 0..127: A[bn, e, j] = sum_i o1[i] * W3[e, i*8+j]
    if (tid < EE) {
        float o1r[HH];
        #pragma unroll
        for (int i = 0; i < HH; i++) o1r[i] = o1s[i];

        const float* w3 = W3 + tid * (HH * HH);
        float a[HH];
        #pragma unroll
        for (int j = 0; j < HH; j++) a[j] = 0.f;
        #pragma unroll
        for (int i = 0; i < HH; i++) {
            #pragma unroll
            for (int j = 0; j < HH; j++)
                a[j] += o1r[i] * w3[i * HH + j];
        }
        float* Ao = g_A + ((size_t)bn * EE + tid) * HH;
        reinterpret_cast<float4*>(Ao)[0] = make_float4(a[0], a[1], a[2], a[3]);
        reinterpret_cast<float4*>(Ao)[1] = make_float4(a[4], a[5], a[6], a[7]);
    }
}

// ---------------------------------------------------------------------------
// Kernel 2: block per (b,n). out[bn, m, e] = b3[e] + sum_j A[bn,e,j]*o2[b,m,j]
// Warp covers all 128 e (4 per lane, registers); sweeps m with smem-broadcast
// o2 reads; one coalesced 512B streaming store per warp per m.
// ---------------------------------------------------------------------------
__global__ void __launch_bounds__(256) main_kernel(
    const float* __restrict__ b3,   // (E,)
    float* __restrict__ out)        // (B,N,N,E)
{
    const int bn   = blockIdx.x;
    const int b    = bn >> 9;          // /512
    const int tid  = threadIdx.x;      // 256 = 8 warps
    const int warp = tid >> 5;
    const int lane = tid & 31;

    __shared__ float4 o2s[NN * HH / 4];   // 1024 float4 = 16 KB

    const float4* o2g = reinterpret_cast<const float4*>(g_o2 + (size_t)b * NN * HH);
    #pragma unroll
    for (int i = tid; i < NN * HH / 4; i += 256)
        o2s[i] = __ldg(o2g + i);

    // A for this lane's e-quad (e = 4*lane .. 4*lane+3): 32 floats in registers
    float a[4][HH];
    const float* Ab = g_A + ((size_t)bn * EE + 4 * lane) * HH;
    #pragma unroll
    for (int q = 0; q < 4; q++) {
        float4 v0 = reinterpret_cast<const float4*>(Ab + q * HH)[0];
        float4 v1 = reinterpret_cast<const float4*>(Ab + q * HH)[1];
        a[q][0] = v0.x; a[q][1] = v0.y; a[q][2] = v0.z; a[q][3] = v0.w;
        a[q][4] = v1.x; a[q][5] = v1.y; a[q][6] = v1.z; a[q][7] = v1.w;
    }
    const float4 bv = reinterpret_cast<const float4*>(b3)[lane];

    __syncthreads();

    // out as float4: row (bn, m) has E/4 = 32 float4; lane owns slot `lane`.
    float4* outp = reinterpret_cast<float4*>(out) + (size_t)bn * NN * (EE / 4) + lane;

    for (int m = warp; m < NN; m += 8) {
        const float4 p  = o2s[m * 2];       // broadcast within warp
        const float4 qv = o2s[m * 2 + 1];
        const float o2r[HH] = {p.x, p.y, p.z, p.w, qv.x, qv.y, qv.z, qv.w};

        float4 acc = bv;
        #pragma unroll
        for (int j = 0; j < HH; j++) {
            acc.x += a[0][j] * o2r[j];
            acc.y += a[1][j] * o2r[j];
            acc.z += a[2][j] * o2r[j];
            acc.w += a[3][j] * o2r[j];
        }
        // streaming store: output is write-once, keep it out of L2
        __stcs(outp + (size_t)m * (EE / 4), acc);
    }
}

extern "C" void kernel_launch(void* const* d_in, const int* in_sizes, int n_in,
                              void* d_out, int out_size)
{
    const float* x   = (const float*)d_in[0];
    const float* W12 = (const float*)d_in[1];
    const float* b12 = (const float*)d_in[2];
    const float* W3  = (const float*)d_in[3];
    const float* b3  = (const float*)d_in[4];
    float* out = (float*)d_out;

    prep_kernel<<<BB * NN, 512>>>(x, W12, b12, W3);
    main_kernel<<<BB * NN, 256>>>(b3, out);
}

// round 6
// speedup vs baseline: 1.2726x; 1.2726x over previous
#include <cuda_runtime.h>

#define BB 2
#define NN 512
#define DD 512
#define HH 8
#define EE 128
#define MSPLIT 4
#define MCH (NN / MSPLIT)   // 128 m per block

// Scratch (no cudaMalloc allowed)
__device__ float g_o2[BB * NN * HH];              // 8K floats
__device__ float g_A [(size_t)BB * NN * EE * HH]; // 1M floats = 4 MB

// ---------------------------------------------------------------------------
// Kernel 1: per (b,n) row — o12 = x@W12^T + b12 ; o2 -> scratch ;
// A[e][j] = sum_i o1[i] * W3[e, i*8+j]  (W3 staged in padded smem: no replays)
// ---------------------------------------------------------------------------
__global__ void __launch_bounds__(512) prep_kernel(
    const float* __restrict__ x,    // (B,N,D)
    const float* __restrict__ W12,  // (16,D)
    const float* __restrict__ b12,  // (16,)
    const float* __restrict__ W3)   // (E,64)
{
    const int bn   = blockIdx.x;
    const int tid  = threadIdx.x;       // 512 threads = 16 warps
    const int warp = tid >> 5;
    const int lane = tid & 31;

    __shared__ float xs[DD];
    __shared__ float o1s[HH];
    __shared__ float w3s[EE * 65];      // pitch 65 -> conflict-free column reads

    const float* xrow = x + (size_t)bn * DD;
    for (int i = tid; i < DD / 4; i += 512)
        reinterpret_cast<float4*>(xs)[i] = reinterpret_cast<const float4*>(xrow)[i];

    // stage W3 (coalesced global read, padded smem write)
    for (int idx = tid; idx < EE * 64; idx += 512) {
        int e = idx >> 6, k = idx & 63;
        w3s[e * 65 + k] = W3[idx];
    }
    __syncthreads();

    // warp w computes o12[bn, w]
    float sum = 0.f;
    const float* w = W12 + warp * DD;
    #pragma unroll 4
    for (int i = lane; i < DD; i += 32)
        sum += xs[i] * w[i];
    #pragma unroll
    for (int o = 16; o; o >>= 1)
        sum += __shfl_xor_sync(0xffffffffu, sum, o);

    if (lane == 0) {
        sum += b12[warp];
        if (warp < HH) o1s[warp] = sum;
        else           g_o2[bn * HH + (warp - HH)] = sum;
    }
    __syncthreads();

    if (tid < EE) {
        float o1r[HH];
        #pragma unroll
        for (int i = 0; i < HH; i++) o1r[i] = o1s[i];

        const float* w3 = w3s + tid * 65;   // conflict-free: bank=(tid+k)%32
        float a[HH];
        #pragma unroll
        for (int j = 0; j < HH; j++) a[j] = 0.f;
        #pragma unroll
        for (int i = 0; i < HH; i++) {
            #pragma unroll
            for (int j = 0; j < HH; j++)
                a[j] += o1r[i] * w3[i * HH + j];
        }
        float* Ao = g_A + ((size_t)bn * EE + tid) * HH;
        reinterpret_cast<float4*>(Ao)[0] = make_float4(a[0], a[1], a[2], a[3]);
        reinterpret_cast<float4*>(Ao)[1] = make_float4(a[4], a[5], a[6], a[7]);
    }
}

// ---------------------------------------------------------------------------
// Kernel 2: block per (bn, m-chunk). out[bn,m,e] = b3[e] + sum_j A[bn,e,j]*o2[b,m,j]
// f32x2 packed FMA over j-pairs (falls back to scalar FFMA pre-sm_100);
// one coalesced 512B streaming store per warp per m.
// ---------------------------------------------------------------------------
#if !defined(__CUDA_ARCH__) || (__CUDA_ARCH__ >= 1000)
#define HAS_F32X2 1
#else
#define HAS_F32X2 0
#endif

__global__ void __launch_bounds__(256) main_kernel(
    const float* __restrict__ b3,   // (E,)
    float* __restrict__ out)        // (B,N,N,E)
{
    const int bn   = blockIdx.x;
    const int b    = bn >> 9;
    const int mc   = blockIdx.y;
    const int tid  = threadIdx.x;      // 256 = 8 warps
    const int warp = tid >> 5;
    const int lane = tid & 31;

    __shared__ float o2s[MCH * HH];    // 4 KB

    const float4* o2g = reinterpret_cast<const float4*>(
        g_o2 + ((size_t)b * NN + (size_t)mc * MCH) * HH);
    for (int i = tid; i < MCH * HH / 4; i += 256)
        reinterpret_cast<float4*>(o2s)[i] = __ldg(o2g + i);

#if HAS_F32X2
    // A for this lane's e-quad, as packed j-pairs (4 e x 4 pairs = 32 regs)
    unsigned long long ap[4][4];
    const ulonglong2* Ab = reinterpret_cast<const ulonglong2*>(
        g_A + ((size_t)bn * EE + 4 * lane) * HH);
    #pragma unroll
    for (int q = 0; q < 4; q++) {
        ulonglong2 v0 = Ab[2 * q];       // j-pairs (0,1),(2,3)
        ulonglong2 v1 = Ab[2 * q + 1];   // j-pairs (4,5),(6,7)
        ap[q][0] = v0.x; ap[q][1] = v0.y; ap[q][2] = v1.x; ap[q][3] = v1.y;
    }
    const float4 bv = reinterpret_cast<const float4*>(b3)[lane];
    unsigned long long bp[4];
    asm("mov.b64 %0, {%1, %2};" : "=l"(bp[0]) : "f"(bv.x), "f"(0.f));
    asm("mov.b64 %0, {%1, %2};" : "=l"(bp[1]) : "f"(bv.y), "f"(0.f));
    asm("mov.b64 %0, {%1, %2};" : "=l"(bp[2]) : "f"(bv.z), "f"(0.f));
    asm("mov.b64 %0, {%1, %2};" : "=l"(bp[3]) : "f"(bv.w), "f"(0.f));
#else
    float a[4][HH];
    const float* Abf = g_A + ((size_t)bn * EE + 4 * lane) * HH;
    #pragma unroll
    for (int q = 0; q < 4; q++) {
        float4 v0 = reinterpret_cast<const float4*>(Abf + q * HH)[0];
        float4 v1 = reinterpret_cast<const float4*>(Abf + q * HH)[1];
        a[q][0] = v0.x; a[q][1] = v0.y; a[q][2] = v0.z; a[q][3] = v0.w;
        a[q][4] = v1.x; a[q][5] = v1.y; a[q][6] = v1.z; a[q][7] = v1.w;
    }
    const float4 bv = reinterpret_cast<const float4*>(b3)[lane];
#endif

    __syncthreads();

    float4* outp = reinterpret_cast<float4*>(out)
                 + ((size_t)bn * NN + (size_t)mc * MCH) * (EE / 4) + lane;

    for (int m = warp; m < MCH; m += 8) {
#if HAS_F32X2
        const ulonglong2* o2p = reinterpret_cast<const ulonglong2*>(o2s + m * HH);
        ulonglong2 u0 = o2p[0];
        ulonglong2 u1 = o2p[1];

        float r[4];
        #pragma unroll
        for (int q = 0; q < 4; q++) {
            unsigned long long acc;
            asm("fma.rn.f32x2 %0, %1, %2, %3;" : "=l"(acc)
                : "l"(ap[q][0]), "l"(u0.x), "l"(bp[q]));
            asm("fma.rn.f32x2 %0, %1, %2, %0;" : "+l"(acc)
                : "l"(ap[q][1]), "l"(u0.y));
            asm("fma.rn.f32x2 %0, %1, %2, %0;" : "+l"(acc)
                : "l"(ap[q][2]), "l"(u1.x));
            asm("fma.rn.f32x2 %0, %1, %2, %0;" : "+l"(acc)
                : "l"(ap[q][3]), "l"(u1.y));
            float lo, hi;
            asm("mov.b64 {%0, %1}, %2;" : "=f"(lo), "=f"(hi) : "l"(acc));
            r[q] = lo + hi;
        }
        __stcs(outp + (size_t)m * (EE / 4), make_float4(r[0], r[1], r[2], r[3]));
#else
        const float4 p  = reinterpret_cast<const float4*>(o2s + m * HH)[0];
        const float4 qv = reinterpret_cast<const float4*>(o2s + m * HH)[1];
        const float o2r[HH] = {p.x, p.y, p.z, p.w, qv.x, qv.y, qv.z, qv.w};
        float4 acc = bv;
        #pragma unroll
        for (int j = 0; j < HH; j++) {
            acc.x += a[0][j] * o2r[j];
            acc.y += a[1][j] * o2r[j];
            acc.z += a[2][j] * o2r[j];
            acc.w += a[3][j] * o2r[j];
        }
        __stcs(outp + (size_t)m * (EE / 4), acc);
#endif
    }
}

extern "C" void kernel_launch(void* const* d_in, const int* in_sizes, int n_in,
                              void* d_out, int out_size)
{
    const float* x   = (const float*)d_in[0];
    const float* W12 = (const float*)d_in[1];
    const float* b12 = (const float*)d_in[2];
    const float* W3  = (const float*)d_in[3];
    const float* b3  = (const float*)d_in[4];
    float* out = (float*)d_out;

    prep_kernel<<<BB * NN, 512>>>(x, W12, b12, W3);
    main_kernel<<<dim3(BB * NN, MSPLIT), 256>>>(b3, out);
}

// round 8
// speedup vs baseline: 1.4551x; 1.1434x over previous
#include <cuda_runtime.h>

#define BB 2
#define NN 512
#define DD 512
#define HH 8
#define EE 128
#define MSPLIT 4
#define MCH (NN / MSPLIT)   // 128 m per block
#define PROWS 8             // bn rows per prep block

// Scratch (no cudaMalloc allowed)
__device__ float g_o2[BB * NN * HH];              // 8K floats
__device__ float g_A [(size_t)BB * NN * EE * HH]; // 1M floats = 4 MB

// ---------------------------------------------------------------------------
// Kernel 1: block handles PROWS bn rows. Stage W3 (padded) in smem ONCE,
// then per row: o12 = x@W12^T + b12 ; o2 -> scratch ;
// A[e][j] = sum_i o1[i]*W3[e,i*8+j].
// Static smem: 33280 + 2048 + 32 B  (< 48 KB limit)
// ---------------------------------------------------------------------------
__global__ void __launch_bounds__(512) prep_kernel(
    const float* __restrict__ x,    // (B,N,D)
    const float* __restrict__ W12,  // (16,D)
    const float* __restrict__ b12,  // (16,)
    const float* __restrict__ W3)   // (E,64)
{
    const int bn0  = blockIdx.x * PROWS;
    const int tid  = threadIdx.x;       // 512 threads = 16 warps
    const int warp = tid >> 5;
    const int lane = tid & 31;

    __shared__ float w3s[EE * 65];      // pitch 65 -> conflict-free column reads
    __shared__ float xs[DD];
    __shared__ float o1s[HH];

    // stage W3 (coalesced global read, padded smem write)
    for (int idx = tid; idx < EE * 64; idx += 512) {
        int e = idx >> 6, k = idx & 63;
        w3s[e * 65 + k] = W3[idx];
    }

    for (int r = 0; r < PROWS; r++) {
        const int bn = bn0 + r;
        __syncthreads();   // xs reuse barrier (also covers W3 staging on r==0)
        const float* xrow = x + (size_t)bn * DD;
        for (int i = tid; i < DD / 4; i += 512)
            reinterpret_cast<float4*>(xs)[i] = reinterpret_cast<const float4*>(xrow)[i];
        __syncthreads();

        // warp w computes o12[bn, w]  (W12 from L2: reused by all blocks)
        float sum = 0.f;
        const float* w = W12 + warp * DD;
        #pragma unroll 4
        for (int i = lane; i < DD; i += 32)
            sum += xs[i] * __ldg(w + i);
        #pragma unroll
        for (int o = 16; o; o >>= 1)
            sum += __shfl_xor_sync(0xffffffffu, sum, o);

        if (lane == 0) {
            sum += b12[warp];
            if (warp < HH) o1s[warp] = sum;
            else           g_o2[bn * HH + (warp - HH)] = sum;
        }
        __syncthreads();

        if (tid < EE) {
            float o1r[HH];
            #pragma unroll
            for (int i = 0; i < HH; i++) o1r[i] = o1s[i];

            const float* w3 = w3s + tid * 65;   // bank=(tid+k)%32: conflict-free
            float a[HH];
            #pragma unroll
            for (int j = 0; j < HH; j++) a[j] = 0.f;
            #pragma unroll
            for (int i = 0; i < HH; i++) {
                #pragma unroll
                for (int j = 0; j < HH; j++)
                    a[j] += o1r[i] * w3[i * HH + j];
            }
            float* Ao = g_A + ((size_t)bn * EE + tid) * HH;
            reinterpret_cast<float4*>(Ao)[0] = make_float4(a[0], a[1], a[2], a[3]);
            reinterpret_cast<float4*>(Ao)[1] = make_float4(a[4], a[5], a[6], a[7]);
        }
    }
}

// ---------------------------------------------------------------------------
// Kernel 2: block per (bn, m-chunk). out[bn,m,e] = b3[e] + sum_j A[bn,e,j]*o2[b,m,j]
// Each lane owns an e-PAIR (16 A regs); warp-pairs split the e-range; scalar
// FFMA; coalesced 256B streaming STG.64 per warp per m. Low regs -> 75% occ.
// ---------------------------------------------------------------------------
__global__ void __launch_bounds__(256, 6) main_kernel(
    const float* __restrict__ b3,   // (E,)
    float* __restrict__ out)        // (B,N,N,E)
{
    const int bn   = blockIdx.x;
    const int b    = bn >> 9;
    const int mc   = blockIdx.y;
    const int tid  = threadIdx.x;      // 256 = 8 warps
    const int warp = tid >> 5;
    const int lane = tid & 31;

    __shared__ float o2s[MCH * HH];    // 4 KB

    const float4* o2g = reinterpret_cast<const float4*>(
        g_o2 + ((size_t)b * NN + (size_t)mc * MCH) * HH);
    for (int i = tid; i < MCH * HH / 4; i += 256)
        reinterpret_cast<float4*>(o2s)[i] = __ldg(o2g + i);

    // lane's e-pair: e = 64*(warp&1) + 2*lane  -> 16 A regs
    const int ebase = ((warp & 1) << 6) + (lane << 1);
    float a0[HH], a1[HH];
    {
        const float4* Ab = reinterpret_cast<const float4*>(
            g_A + ((size_t)bn * EE + ebase) * HH);
        float4 v0 = Ab[0], v1 = Ab[1], v2 = Ab[2], v3 = Ab[3];
        a0[0]=v0.x; a0[1]=v0.y; a0[2]=v0.z; a0[3]=v0.w;
        a0[4]=v1.x; a0[5]=v1.y; a0[6]=v1.z; a0[7]=v1.w;
        a1[0]=v2.x; a1[1]=v2.y; a1[2]=v2.z; a1[3]=v2.w;
        a1[4]=v3.x; a1[5]=v3.y; a1[6]=v3.z; a1[7]=v3.w;
    }
    const float2 bv = reinterpret_cast<const float2*>(b3)[ebase >> 1];

    __syncthreads();

    // out as float2: row (bn,m) has EE/2 = 64 float2; lane owns slot ebase/2
    float2* outp = reinterpret_cast<float2*>(out)
                 + ((size_t)bn * NN + (size_t)mc * MCH) * (EE / 2) + (ebase >> 1);

    for (int m = (warp >> 1); m < MCH; m += 4) {
        const float4 p  = reinterpret_cast<const float4*>(o2s + m * HH)[0];
        const float4 qv = reinterpret_cast<const float4*>(o2s + m * HH)[1];
        const float o2r[HH] = {p.x, p.y, p.z, p.w, qv.x, qv.y, qv.z, qv.w};

        float ax = bv.x, ay = bv.y;
        #pragma unroll
        for (int j = 0; j < HH; j++) {
            ax += a0[j] * o2r[j];
            ay += a1[j] * o2r[j];
        }
        __stcs(outp + (size_t)m * (EE / 2), make_float2(ax, ay));
    }
}

extern "C" void kernel_launch(void* const* d_in, const int* in_sizes, int n_in,
                              void* d_out, int out_size)
{
    const float* x   = (const float*)d_in[0];
    const float* W12 = (const float*)d_in[1];
    const float* b12 = (const float*)d_in[2];
    const float* W3  = (const float*)d_in[3];
    const float* b3  = (const float*)d_in[4];
    float* out = (float*)d_out;

    prep_kernel<<<BB * NN / PROWS, 512>>>(x, W12, b12, W3);
    main_kernel<<<dim3(BB * NN, MSPLIT), 256>>>(b3, out);
}

// round 10
// speedup vs baseline: 1.6160x; 1.1106x over previous
#include <cuda_runtime.h>

#define BB 2
#define NN 512
#define DD 512
#define HH 8
#define EE 128
#define MSPLIT 4
#define MCH (NN / MSPLIT)   // 128 m per block
#define PR 4                // bn rows per prep block, processed in PARALLEL

// Scratch (no cudaMalloc allowed)
__device__ float g_o2[BB * NN * HH];              // 8K floats
__device__ float g_A [(size_t)BB * NN * EE * HH]; // 1M floats = 4 MB

// ---------------------------------------------------------------------------
// Kernel 1: block handles PR=4 bn rows in parallel.
//   Phase A: warp h computes o12[bn0+r, h] for r=0..3 (4 ILP dot products).
//   Phase B: all 512 threads: (r, e) -> A[e][j] = sum_i o1[i]*W3[e, i*8+j].
// Static smem: 33280 (w3s) + 8192 (xs) + 128 (o1s) = 41.6 KB < 48 KB.
// ---------------------------------------------------------------------------
__global__ void __launch_bounds__(512) prep_kernel(
    const float* __restrict__ x,    // (B,N,D)
    const float* __restrict__ W12,  // (16,D)
    const float* __restrict__ b12,  // (16,)
    const float* __restrict__ W3)   // (E,64)
{
    const int bn0  = blockIdx.x * PR;
    const int tid  = threadIdx.x;       // 512 threads = 16 warps
    const int warp = tid >> 5;          // = h index in phase A
    const int lane = tid & 31;

    __shared__ float w3s[EE * 65];      // pitch 65 -> conflict-free column reads
    __shared__ float xs[PR * DD];
    __shared__ float o1s[PR][HH];

    // stage W3 (padded) and the 4 x rows
    for (int idx = tid; idx < EE * 64; idx += 512) {
        int e = idx >> 6, k = idx & 63;
        w3s[e * 65 + k] = W3[idx];
    }
    {
        const float4* xg = reinterpret_cast<const float4*>(x + (size_t)bn0 * DD);
        for (int i = tid; i < PR * DD / 4; i += 512)
            reinterpret_cast<float4*>(xs)[i] = __ldg(xg + i);
    }
    __syncthreads();

    // Phase A: warp h, 4 rows at once (W12 row reused, 4-way ILP)
    {
        float a0 = 0.f, a1 = 0.f, a2 = 0.f, a3 = 0.f;
        const float* w = W12 + warp * DD;
        #pragma unroll 4
        for (int i = lane; i < DD; i += 32) {
            const float wv = __ldg(w + i);
            a0 += wv * xs[0 * DD + i];
            a1 += wv * xs[1 * DD + i];
            a2 += wv * xs[2 * DD + i];
            a3 += wv * xs[3 * DD + i];
        }
        #pragma unroll
        for (int o = 16; o; o >>= 1) {
            a0 += __shfl_xor_sync(0xffffffffu, a0, o);
            a1 += __shfl_xor_sync(0xffffffffu, a1, o);
            a2 += __shfl_xor_sync(0xffffffffu, a2, o);
            a3 += __shfl_xor_sync(0xffffffffu, a3, o);
        }
        if (lane == 0) {
            const float bb = b12[warp];
            float v[PR] = {a0 + bb, a1 + bb, a2 + bb, a3 + bb};
            #pragma unroll
            for (int r = 0; r < PR; r++) {
                if (warp < HH) o1s[r][warp] = v[r];
                else           g_o2[(bn0 + r) * HH + (warp - HH)] = v[r];
            }
        }
    }
    __syncthreads();

    // Phase B: all threads. r = tid/128, e = tid%128.
    {
        const int r = tid >> 7;
        const int e = tid & 127;

        float o1r[HH];
        #pragma unroll
        for (int i = 0; i < HH; i++) o1r[i] = o1s[r][i];   // smem broadcast

        const float* w3 = w3s + e * 65;     // bank=(e+c)%32: conflict-free
        float a[HH];
        #pragma unroll
        for (int j = 0; j < HH; j++) a[j] = 0.f;
        #pragma unroll
        for (int i = 0; i < HH; i++) {
            #pragma unroll
            for (int j = 0; j < HH; j++)
                a[j] += o1r[i] * w3[i * HH + j];
        }
        float* Ao = g_A + ((size_t)(bn0 + r) * EE + e) * HH;
        reinterpret_cast<float4*>(Ao)[0] = make_float4(a[0], a[1], a[2], a[3]);
        reinterpret_cast<float4*>(Ao)[1] = make_float4(a[4], a[5], a[6], a[7]);
    }
}

// ---------------------------------------------------------------------------
// Kernel 2: block per (bn, m-chunk). out[bn,m,e] = b3[e] + sum_j A[bn,e,j]*o2[b,m,j]
// Each lane owns an e-PAIR (16 A regs); warp-pairs split the e-range; unrolled
// compile-time m loop (ILP across 8 iters); coalesced STG.64 streaming stores.
// ---------------------------------------------------------------------------
__global__ void __launch_bounds__(256, 6) main_kernel(
    const float* __restrict__ b3,   // (E,)
    float* __restrict__ out)        // (B,N,N,E)
{
    const int bn   = blockIdx.x;
    const int b    = bn >> 9;
    const int mc   = blockIdx.y;
    const int tid  = threadIdx.x;      // 256 = 8 warps
    const int warp = tid >> 5;
    const int lane = tid & 31;

    __shared__ float o2s[MCH * HH];    // 4 KB

    const float4* o2g = reinterpret_cast<const float4*>(
        g_o2 + ((size_t)b * NN + (size_t)mc * MCH) * HH);
    for (int i = tid; i < MCH * HH / 4; i += 256)
        reinterpret_cast<float4*>(o2s)[i] = __ldg(o2g + i);

    // lane's e-pair: e = 64*(warp&1) + 2*lane  -> 16 A regs
    const int ebase = ((warp & 1) << 6) + (lane << 1);
    float a0[HH], a1[HH];
    {
        const float4* Ab = reinterpret_cast<const float4*>(
            g_A + ((size_t)bn * EE + ebase) * HH);
        float4 v0 = Ab[0], v1 = Ab[1], v2 = Ab[2], v3 = Ab[3];
        a0[0]=v0.x; a0[1]=v0.y; a0[2]=v0.z; a0[3]=v0.w;
        a0[4]=v1.x; a0[5]=v1.y; a0[6]=v1.z; a0[7]=v1.w;
        a1[0]=v2.x; a1[1]=v2.y; a1[2]=v2.z; a1[3]=v2.w;
        a1[4]=v3.x; a1[5]=v3.y; a1[6]=v3.z; a1[7]=v3.w;
    }
    const float2 bv = reinterpret_cast<const float2*>(b3)[ebase >> 1];

    __syncthreads();

    // out as float2: row (bn,m) has EE/2 = 64 float2; lane owns slot ebase/2
    const int m0 = warp >> 1;          // 0..3
    float2* op = reinterpret_cast<float2*>(out)
               + ((size_t)bn * NN + (size_t)mc * MCH + m0) * (EE / 2) + (ebase >> 1);
    const float4* o2v = reinterpret_cast<const float4*>(o2s) + m0 * 2;

    #pragma unroll 8
    for (int it = 0; it < MCH / 4; ++it) {
        const float4 p  = o2v[0];
        const float4 qv = o2v[1];

        float ax = bv.x, ay = bv.y;
        ax += a0[0]*p.x;  ay += a1[0]*p.x;
        ax += a0[1]*p.y;  ay += a1[1]*p.y;
        ax += a0[2]*p.z;  ay += a1[2]*p.z;
        ax += a0[3]*p.w;  ay += a1[3]*p.w;
        ax += a0[4]*qv.x; ay += a1[4]*qv.x;
        ax += a0[5]*qv.y; ay += a1[5]*qv.y;
        ax += a0[6]*qv.z; ay += a1[6]*qv.z;
        ax += a0[7]*qv.w; ay += a1[7]*qv.w;

        __stcs(op, make_float2(ax, ay));
        op  += 4 * (EE / 2);   // next m (stride 4)
        o2v += 4 * 2;
    }
}

extern "C" void kernel_launch(void* const* d_in, const int* in_sizes, int n_in,
                              void* d_out, int out_size)
{
    const float* x   = (const float*)d_in[0];
    const float* W12 = (const float*)d_in[1];
    const float* b12 = (const float*)d_in[2];
    const float* W3  = (const float*)d_in[3];
    const float* b3  = (const float*)d_in[4];
    float* out = (float*)d_out;

    prep_kernel<<<BB * NN / PR, 512>>>(x, W12, b12, W3);
    main_kernel<<<dim3(BB * NN, MSPLIT), 256>>>(b3, out);
}